// round 13
// baseline (speedup 1.0000x reference)
#include <cuda_runtime.h>
#include <cuda_bf16.h>

// CausalSequenceCML: 16 fused steps of depthwise-causal-conv logistic CML.
// B=4, T=4096, C=512, K=4, STEPS=16.
//
// Round-13: R12 geometry (64512 cell-units/SM — enumerated optimum) with
// the per-step serial head pipelined away:
//  - CC=8 x SS=32 x LL=18, 256 threads, occ 4. Same TILE=576/VALID=528/
//    NTILES=8/grid=2048 as R12, but 15 interior cells per step.
//  - BAR.SYNC is defer-blocking on sm_100a: after the barrier we run the
//    interior sweep (registers only, ~70 FMAs) while the barrier resolves;
//    the neighbor LDS is issued mid-interior and consumed only by the
//    final 3 head cells -> barrier + LDS latency hidden under FMAs.
//  - FMA count and per-cell math identical to R12 (5 FMA/cell, tails reused).

#define Bdim 4
#define Tdim 4096
#define Cdim 512
#define NSTEPS 16
#define CC 8                 // channels per block (thread c = tid&7)
#define SS 32                // time strips per block
#define LL 18                // cells per thread
#define TILE (SS * LL)       // 576
#define HALO 48              // 3 * NSTEPS
#define VALID (TILE - HALO)  // 528
#define NTILES ((Tdim + VALID - 1) / VALID)  // 8

__global__ void __launch_bounds__(CC * SS, 4)
cml_kernel(const float* __restrict__ drive,
           const float* __restrict__ r,
           const float* __restrict__ eps,
           const float* __restrict__ beta,
           const float* __restrict__ Kc,
           float* __restrict__ out)
{
    // boundary m' values, phantom zero strip at index 0: [buf][strip+1][3][ch]
    __shared__ float bm[2][SS + 1][3][CC];

    const int tid = threadIdx.x;
    const int c   = tid & (CC - 1);
    const int s   = tid / CC;
    const int cg  = blockIdx.y * CC + c;
    const int b   = blockIdx.z;
    const int gt0 = (int)blockIdx.x * VALID - HALO;
    const int base = b * (Tdim * Cdim);

    // zero-pad phantom strip (both buffers)
    if (s == 0) {
#pragma unroll
        for (int j = 0; j < 3; j++) {
            bm[0][0][j][c] = 0.0f;
            bm[1][0][j][c] = 0.0f;
        }
    }

    // per-channel constants; fold r into the conv weights
    const float rr = r[cg];
    const float ee = eps[cg];
    const float bb = beta[cg];
    const float k0 = Kc[cg * 4 + 0];
    const float k1 = Kc[cg * 4 + 1];
    const float k2 = Kc[cg * 4 + 2];
    const float k3 = Kc[cg * 4 + 3];
    const float onemb = 1.0f - bb;
    const float A  = onemb * (1.0f - ee);
    const float Bc = onemb * ee;
    const float v3 = fmaf(Bc, k3, A) * rr;   // coeff of m'[t]
    const float v2 = Bc * k2 * rr;           // m'[t-1]
    const float v1 = Bc * k1 * rr;           // m'[t-2]
    const float v0 = Bc * k0 * rr;           // m'[t-3]

    // load drive -> g init, D = beta * drive (step-invariant, in regs)
    float g[LL], D[LL];
#pragma unroll
    for (int i = 0; i < LL; i++) {
        const int gt = gt0 + s * LL + i;
        float d = 0.0f;
        if (gt >= 0 && gt < Tdim)
            d = drive[base + gt * Cdim + cg];
        g[i] = d;
        D[i] = bb * d;
    }

#pragma unroll 1
    for (int step = 0; step < NSTEPS; step++) {
        float (*buf)[3][CC] = bm[step & 1];
        // tails: m' of this strip's last 3 cells -> slot s+1 (kept live,
        // reused for the sweep's last 3 cells)
        const float gA = g[LL - 3], gB = g[LL - 2], gC = g[LL - 1];
        const float tA = fmaf(-gA, gA, gA);
        const float tB = fmaf(-gB, gB, gB);
        const float tC = fmaf(-gC, gC, gC);
        buf[s + 1][0][c] = tA;
        buf[s + 1][1][c] = tB;
        buf[s + 1][2][c] = tC;
        __syncthreads();   // defer-blocking: no smem consumer until the LDS below

        // head m' (local, registers only) — seeds the interior chain
        const float h0 = fmaf(-g[0], g[0], g[0]);
        const float h1 = fmaf(-g[1], g[1], g[1]);
        const float h2 = fmaf(-g[2], g[2], g[2]);

        float m3 = h0, m2 = h1, m1 = h2;
        // interior part 1: cells 3..8 (pure register FMAs; barrier resolves
        // in the background)
#pragma unroll
        for (int i = 3; i < 9; i++) {
            const float gi = g[i];
            const float m0 = fmaf(-gi, gi, gi);
            float acc = fmaf(v3, m0, D[i]);
            acc = fmaf(v2, m1, acc);
            acc = fmaf(v1, m2, acc);
            g[i] = fmaf(v0, m3, acc);
            m3 = m2; m2 = m1; m1 = m0;
        }

        // neighbor m' (prev strip's tails; slot s; phantom zeros for s=0).
        // Issued here, consumed only by the head cells at the end.
        const float p1 = buf[s][2][c];
        const float p2 = buf[s][1][c];
        const float p3 = buf[s][0][c];

        // interior part 2: cells 9..LL-1 (tails reused for the last 3)
#pragma unroll
        for (int i = 9; i < LL; i++) {
            const float gi = g[i];
            const float m0 = (i < LL - 3) ? fmaf(-gi, gi, gi)
                           : (i == LL - 3 ? tA : (i == LL - 2 ? tB : tC));
            float acc = fmaf(v3, m0, D[i]);
            acc = fmaf(v2, m1, acc);
            acc = fmaf(v1, m2, acc);
            g[i] = fmaf(v0, m3, acc);
            m3 = m2; m2 = m1; m1 = m0;
        }

        // head cells 0..2 consume the neighbor values last
        {
            float acc = fmaf(v3, h0, D[0]);
            acc = fmaf(v2, p1, acc);
            acc = fmaf(v1, p2, acc);
            g[0] = fmaf(v0, p3, acc);
        }
        {
            float acc = fmaf(v3, h1, D[1]);
            acc = fmaf(v2, h0, acc);
            acc = fmaf(v1, p1, acc);
            g[1] = fmaf(v0, p2, acc);
        }
        {
            float acc = fmaf(v3, h2, D[2]);
            acc = fmaf(v2, h1, acc);
            acc = fmaf(v1, h0, acc);
            g[2] = fmaf(v0, p1, acc);
        }
    }

    // clip + store valid region
#pragma unroll
    for (int i = 0; i < LL; i++) {
        const int lt = s * LL + i;
        const int gt = gt0 + lt;
        if (lt >= HALO && gt < Tdim) {
            const float v = fminf(fmaxf(g[i], 1.0e-4f), 1.0f - 1.0e-4f);
            out[base + gt * Cdim + cg] = v;
        }
    }
}

extern "C" void kernel_launch(void* const* d_in, const int* in_sizes, int n_in,
                              void* d_out, int out_size)
{
    const float* drive = (const float*)d_in[0];
    const float* r     = (const float*)d_in[1];
    const float* eps   = (const float*)d_in[2];
    const float* beta  = (const float*)d_in[3];
    const float* Kc    = (const float*)d_in[4];
    float* out = (float*)d_out;

    dim3 grid(NTILES, Cdim / CC, Bdim);   // 8 x 64 x 4 = 2048 CTAs
    cml_kernel<<<grid, CC * SS>>>(drive, r, eps, beta, Kc, out);
}

// round 15
// speedup vs baseline: 1.0531x; 1.0531x over previous
#include <cuda_runtime.h>
#include <cuda_bf16.h>

// CausalSequenceCML: 16 fused steps of depthwise-causal-conv logistic CML.
// B=4, T=4096, C=512, K=4, STEPS=16.
//
// Round-15: resubmit of R14 (round 14 died on a broker infra failure — same
// transient as rounds 0/9; no kernel signal was produced).
// R12 step body exactly (best: 45.3us, 93% of the mixed-rt FFMA cap),
// geometry refined to the enumerated minimum tile-cell count:
//  - CC=8 x SS=40 x LL=14, 320 threads. TILE=560, VALID=512, NTILES=8:
//    8*512 = 4096 EXACT; tile cells 4480 vs R12's 4608 (-2.8% FFMA).
//  - launch_bounds(320,3): 68-reg cap, state g[14]+D[14]=28 (~58 total),
//    no spill (R13 lesson: do not sit on the reg cap).
//  - exchange banking conflict-free: (24s + 8j + c) mod 32 covers all banks.

#define Bdim 4
#define Tdim 4096
#define Cdim 512
#define NSTEPS 16
#define CC 8                 // channels per block (thread c = tid&7)
#define SS 40                // time strips per block
#define LL 14                // cells per thread
#define TILE (SS * LL)       // 560
#define HALO 48              // 3 * NSTEPS
#define VALID (TILE - HALO)  // 512
#define NTILES (Tdim / VALID) // 8, exact

__global__ void __launch_bounds__(CC * SS, 3)
cml_kernel(const float* __restrict__ drive,
           const float* __restrict__ r,
           const float* __restrict__ eps,
           const float* __restrict__ beta,
           const float* __restrict__ Kc,
           float* __restrict__ out)
{
    // boundary m' values, phantom zero strip at index 0: [buf][strip+1][3][ch]
    __shared__ float bm[2][SS + 1][3][CC];

    const int tid = threadIdx.x;
    const int c   = tid & (CC - 1);
    const int s   = tid / CC;
    const int cg  = blockIdx.y * CC + c;
    const int b   = blockIdx.z;
    const int gt0 = (int)blockIdx.x * VALID - HALO;
    const int base = b * (Tdim * Cdim);

    // zero-pad phantom strip (both buffers)
    if (s == 0) {
#pragma unroll
        for (int j = 0; j < 3; j++) {
            bm[0][0][j][c] = 0.0f;
            bm[1][0][j][c] = 0.0f;
        }
    }

    // per-channel constants; fold r into the conv weights
    const float rr = r[cg];
    const float ee = eps[cg];
    const float bb = beta[cg];
    const float k0 = Kc[cg * 4 + 0];
    const float k1 = Kc[cg * 4 + 1];
    const float k2 = Kc[cg * 4 + 2];
    const float k3 = Kc[cg * 4 + 3];
    const float onemb = 1.0f - bb;
    const float A  = onemb * (1.0f - ee);
    const float Bc = onemb * ee;
    const float v3 = fmaf(Bc, k3, A) * rr;   // coeff of m'[t]
    const float v2 = Bc * k2 * rr;           // m'[t-1]
    const float v1 = Bc * k1 * rr;           // m'[t-2]
    const float v0 = Bc * k0 * rr;           // m'[t-3]

    // load drive -> g init, D = beta * drive (step-invariant, in regs)
    float g[LL], D[LL];
#pragma unroll
    for (int i = 0; i < LL; i++) {
        const int gt = gt0 + s * LL + i;
        float d = 0.0f;
        if (gt >= 0 && gt < Tdim)
            d = drive[base + gt * Cdim + cg];
        g[i] = d;
        D[i] = bb * d;
    }

#pragma unroll 1
    for (int step = 0; step < NSTEPS; step++) {
        float (*buf)[3][CC] = bm[step & 1];
        // boundary: m' of this strip's last 3 cells -> slot s+1 (kept live
        // and reused below for the sweep's last 3 cells)
        const float gA = g[LL - 3], gB = g[LL - 2], gC = g[LL - 1];
        const float tA = fmaf(-gA, gA, gA);
        const float tB = fmaf(-gB, gB, gB);
        const float tC = fmaf(-gC, gC, gC);
        buf[s + 1][0][c] = tA;
        buf[s + 1][1][c] = tB;
        buf[s + 1][2][c] = tC;
        __syncthreads();

        float m3 = buf[s][0][c];
        float m2 = buf[s][1][c];
        float m1 = buf[s][2][c];
        // main sweep: 5 FMA/cell; last-3 m' reused (compile-time select)
#pragma unroll
        for (int i = 0; i < LL; i++) {
            const float gi = g[i];
            const float m0 = (i < LL - 3) ? fmaf(-gi, gi, gi)
                           : (i == LL - 3 ? tA : (i == LL - 2 ? tB : tC));
            float acc = fmaf(v3, m0, D[i]);
            acc = fmaf(v2, m1, acc);
            acc = fmaf(v1, m2, acc);
            g[i] = fmaf(v0, m3, acc);
            m3 = m2; m2 = m1; m1 = m0;
        }
    }

    // clip + store valid region
#pragma unroll
    for (int i = 0; i < LL; i++) {
        const int lt = s * LL + i;
        const int gt = gt0 + lt;
        if (lt >= HALO && gt < Tdim) {
            const float v = fminf(fmaxf(g[i], 1.0e-4f), 1.0f - 1.0e-4f);
            out[base + gt * Cdim + cg] = v;
        }
    }
}

extern "C" void kernel_launch(void* const* d_in, const int* in_sizes, int n_in,
                              void* d_out, int out_size)
{
    const float* drive = (const float*)d_in[0];
    const float* r     = (const float*)d_in[1];
    const float* eps   = (const float*)d_in[2];
    const float* beta  = (const float*)d_in[3];
    const float* Kc    = (const float*)d_in[4];
    float* out = (float*)d_out;

    dim3 grid(NTILES, Cdim / CC, Bdim);   // 8 x 64 x 4 = 2048 CTAs
    cml_kernel<<<grid, CC * SS>>>(drive, r, eps, beta, Kc, out);
}